// round 8
// baseline (speedup 1.0000x reference)
#include <cuda_runtime.h>
#include <cuda_bf16.h>

// CapsuleRoutingPooling collapses analytically:
// softmax over a size-1 axis == 1 -> the dynamic-routing loop is a no-op
// w.r.t. the output. Kernel = squash( 2x2 sum-pool of the D=16 vectors ).
//
// Shapes: B=16, C=64, H=W=64, D=16, k=2 -> nH=nW=32,
// output vectors = 16*64*32*32 = 1,048,576.
//
// FINAL configuration (R4/R7 layout, best bench 52.86us):
// 4 threads per output vector, one float4 each; plain cached loads;
// __stcs streaming stores; oversubscribed grid. This round: 512-thread
// blocks (the one untested knob; per-thread code identical).
// Measured at ~6.6 TB/s HBM (83% of spec) — the achievable ceiling for
// this 4:1 read:write streaming mix; traffic (320 MB) is the mandatory
// minimum. ILP depth, cache hints, dense request shaping, and persistent
// grids all measured neutral-or-worse (R2/R3/R5/R6).

static constexpr int NVEC = 16 * 64 * 32 * 32;     // output vectors
static constexpr int NTHREADS_TOTAL = NVEC * 4;    // 4,194,304
static constexpr int THREADS = 512;
static constexpr int BLOCKS  = NTHREADS_TOTAL / THREADS;   // 8192

__global__ void __launch_bounds__(THREADS)
capsule_pool_squash_kernel(const float* __restrict__ inp, float* __restrict__ out) {
    int gid  = blockIdx.x * THREADS + threadIdx.x;
    int v    = gid >> 2;      // output vector id
    int lane = gid & 3;       // which float4 of the D=16 vector

    // v = ((bc)*32 + nh)*32 + nw
    int bc = v >> 10;         // b*C + c   (0..1023)
    int t  = v & 1023;
    int nh = t >> 5;
    int nw = t & 31;

    // input float4 indexing: row (b,c,h) has W*D/4 = 256 float4s; w step = D/4 = 4
    const float4* __restrict__ in4 = (const float4*)inp;
    int base4 = (bc * 64 + (nh << 1)) * 256 + (nw << 3) + lane;

    float4 p00 = in4[base4];
    float4 p01 = in4[base4 + 4];
    float4 p10 = in4[base4 + 256];
    float4 p11 = in4[base4 + 260];

    float4 s;
    s.x = (p00.x + p01.x) + (p10.x + p11.x);
    s.y = (p00.y + p01.y) + (p10.y + p11.y);
    s.z = (p00.z + p01.z) + (p10.z + p11.z);
    s.w = (p00.w + p01.w) + (p10.w + p11.w);

    // squared norm over D=16: reduce across the 4 lanes of this vector
    float sq = s.x * s.x + s.y * s.y + s.z * s.z + s.w * s.w;
    sq += __shfl_xor_sync(0xffffffffu, sq, 1);
    sq += __shfl_xor_sync(0xffffffffu, sq, 2);

    // squash scale: sq/(1+sq) * 1/(sqrt(sq)+1e-8)
    float scale = sq / ((1.0f + sq) * (sqrtf(sq) + 1e-8f));

    float4 o;
    o.x = s.x * scale;
    o.y = s.y * scale;
    o.z = s.z * scale;
    o.w = s.w * scale;

    __stcs(&((float4*)out)[(v << 2) + lane], o);
}

extern "C" void kernel_launch(void* const* d_in, const int* in_sizes, int n_in,
                              void* d_out, int out_size) {
    const float* inp = (const float*)d_in[0];
    float* out = (float*)d_out;
    capsule_pool_squash_kernel<<<BLOCKS, THREADS>>>(inp, out);
}